// round 1
// baseline (speedup 1.0000x reference)
#include <cuda_runtime.h>
#include <cstdint>
#include <math.h>

// ---------------- problem constants ----------------
constexpr int N_NODES = 50000;
constexpr int N0      = 30000;           // type-0 nodes (featured), rows [0,N0)
constexpr int N_EDGES = 600000;
constexpr int NT      = 8;               // edge types
constexpr int IN_C    = 128;
constexpr int HID_C   = 128;
constexpr int OUT_C   = 40;

// ---------------- device scratch (static, no runtime alloc) ----------------
__device__ int   g_cnt[NT * N_NODES];                       // edge counts per (type,dst)
__device__ float g_xt1[(size_t)N_NODES * (NT * HID_C)];     // [n][t*128+o]  204.8 MB
__device__ float g_h1 [(size_t)N_NODES * HID_C];            // layer-1 output (pre-relu) 25.6 MB
__device__ float g_xt2[(size_t)N_NODES * (NT * OUT_C)];     // [n][t*40+o]   64 MB

// ---------------- small kernels ----------------
__global__ void zero_cnt_kernel() {
    int i = blockIdx.x * blockDim.x + threadIdx.x;
    if (i < NT * N_NODES) g_cnt[i] = 0;
}

__global__ void count_kernel(const int* __restrict__ dst, const int* __restrict__ etype) {
    int e = blockIdx.x * blockDim.x + threadIdx.x;
    if (e < N_EDGES) atomicAdd(&g_cnt[etype[e] * N_NODES + dst[e]], 1);
}

// ---------------- tiled fp32 GEMM ----------------
// Out[row0+gm][c] = sum_k A(row0+gm, k) * W[c*128 + k]   (+ Bias[c])
// ASRC==0: A(r,k) = r < N0 ? Aa[r*128+k] : Ab[(r-N0)*128+k]   (input concat)
// ASRC==1: A(r,k) = Aa[r*128+k]   (optionally relu'd)
// 256 threads. BM=64, BK=32, TM=4, BN = 16*TN.
template<int ASRC, bool RELU, bool BIAS, int TN>
__global__ void __launch_bounds__(256) sgemm_kernel(
    const float* __restrict__ Aa, const float* __restrict__ Ab,
    const float* __restrict__ W,  const float* __restrict__ Bias,
    float* __restrict__ Out, int row0, int nrows, int ncols, int out_ld)
{
    constexpr int BM = 64, BK = 32, TM = 4;
    constexpr int BN = 16 * TN;
    __shared__ float As[BK][BM];
    __shared__ float Ws[BK][BN];

    const int tid   = threadIdx.x;
    const int mbase = blockIdx.x * BM;
    const int nbase = blockIdx.y * BN;
    const int ty    = tid >> 4;     // 0..15 row group
    const int tx    = tid & 15;     // 0..15 col group

    float acc[TM][TN];
#pragma unroll
    for (int i = 0; i < TM; i++)
#pragma unroll
        for (int j = 0; j < TN; j++) acc[i][j] = 0.f;

    const int ar = tid >> 3;          // 0..31
    const int ak = (tid & 7) << 2;    // 0,4,...,28

    for (int k0 = 0; k0 < 128; k0 += BK) {
        // --- load A tile (64 rows x 32 k), stored transposed As[k][m] ---
#pragma unroll
        for (int p = 0; p < 2; p++) {
            int m  = ar + p * 32;
            int gm = mbase + m;
            float4 v = make_float4(0.f, 0.f, 0.f, 0.f);
            if (gm < nrows) {
                const float* srcp;
                if (ASRC == 0) {
                    int grow = row0 + gm;
                    srcp = (grow < N0) ? (Aa + (size_t)grow * 128)
                                       : (Ab + (size_t)(grow - N0) * 128);
                } else {
                    srcp = Aa + (size_t)(row0 + gm) * 128;
                }
                v = *reinterpret_cast<const float4*>(srcp + k0 + ak);
                if (RELU) {
                    v.x = fmaxf(v.x, 0.f); v.y = fmaxf(v.y, 0.f);
                    v.z = fmaxf(v.z, 0.f); v.w = fmaxf(v.w, 0.f);
                }
            }
            As[ak + 0][m] = v.x; As[ak + 1][m] = v.y;
            As[ak + 2][m] = v.z; As[ak + 3][m] = v.w;
        }
        // --- load W tile (BN cols x 32 k), stored Ws[k][c] ---
#pragma unroll
        for (int p = 0; p < BN / 32; p++) {
            int c  = ar + p * 32;
            int gc = nbase + c;
            float4 v = make_float4(0.f, 0.f, 0.f, 0.f);
            if (gc < ncols)
                v = *reinterpret_cast<const float4*>(W + (size_t)gc * 128 + k0 + ak);
            Ws[ak + 0][c] = v.x; Ws[ak + 1][c] = v.y;
            Ws[ak + 2][c] = v.z; Ws[ak + 3][c] = v.w;
        }
        __syncthreads();

#pragma unroll
        for (int kk = 0; kk < BK; kk++) {
            float a[TM], w[TN];
            float4 a4 = *reinterpret_cast<const float4*>(&As[kk][ty * TM]);
            a[0] = a4.x; a[1] = a4.y; a[2] = a4.z; a[3] = a4.w;
#pragma unroll
            for (int q = 0; q < TN / 4; q++) {
                float4 w4 = *reinterpret_cast<const float4*>(&Ws[kk][tx * TN + q * 4]);
                w[q * 4 + 0] = w4.x; w[q * 4 + 1] = w4.y;
                w[q * 4 + 2] = w4.z; w[q * 4 + 3] = w4.w;
            }
#pragma unroll
            for (int i = 0; i < TM; i++)
#pragma unroll
                for (int j = 0; j < TN; j++)
                    acc[i][j] = fmaf(a[i], w[j], acc[i][j]);
        }
        __syncthreads();
    }

#pragma unroll
    for (int i = 0; i < TM; i++) {
        int gm = mbase + ty * TM + i;
        if (gm >= nrows) continue;
        size_t orow = (size_t)(row0 + gm) * out_ld;
#pragma unroll
        for (int j = 0; j < TN; j++) {
            int c = nbase + tx * TN + j;
            if (c < ncols) {
                float v = acc[i][j];
                if (BIAS) v += Bias[c];
                Out[orow + c] = v;
            }
        }
    }
}

// ---------------- edge scatter kernels (warp per edge) ----------------
__global__ void edge1_kernel(const int* __restrict__ src, const int* __restrict__ dst,
                             const int* __restrict__ etype)
{
    int e = (blockIdx.x * blockDim.x + threadIdx.x) >> 5;
    if (e >= N_EDGES) return;
    int lane = threadIdx.x & 31;
    int s = src[e], d = dst[e], t = etype[e];
    int c = g_cnt[t * N_NODES + d];
    float inv = 1.0f / (float)(c < 1 ? 1 : c);
    const float4* xs = reinterpret_cast<const float4*>(&g_xt1[(size_t)s * (NT * HID_C) + t * HID_C]);
    float4 v = xs[lane];
    float* op = &g_h1[(size_t)d * HID_C + lane * 4];
    atomicAdd(op + 0, v.x * inv);
    atomicAdd(op + 1, v.y * inv);
    atomicAdd(op + 2, v.z * inv);
    atomicAdd(op + 3, v.w * inv);
}

__global__ void edge2_kernel(const int* __restrict__ src, const int* __restrict__ dst,
                             const int* __restrict__ etype, float* __restrict__ out)
{
    int e = (blockIdx.x * blockDim.x + threadIdx.x) >> 5;
    if (e >= N_EDGES) return;
    int lane = threadIdx.x & 31;
    int s = src[e], d = dst[e], t = etype[e];
    int c = g_cnt[t * N_NODES + d];
    float inv = 1.0f / (float)(c < 1 ? 1 : c);
    const float* xs = &g_xt2[(size_t)s * (NT * OUT_C) + t * OUT_C];
    float* op = out + (size_t)d * OUT_C;
    atomicAdd(op + lane, xs[lane] * inv);
    if (lane < OUT_C - 32)
        atomicAdd(op + 32 + lane, xs[32 + lane] * inv);
}

// ---------------- log-softmax over 40 classes (warp per node) ----------------
__global__ void logsoftmax_kernel(float* __restrict__ out)
{
    int n = (blockIdx.x * blockDim.x + threadIdx.x) >> 5;
    if (n >= N_NODES) return;
    int lane = threadIdx.x & 31;
    float* row = out + (size_t)n * OUT_C;
    float a = row[lane];
    float b = (lane < OUT_C - 32) ? row[lane + 32] : -INFINITY;
    float m = fmaxf(a, b);
#pragma unroll
    for (int off = 16; off > 0; off >>= 1)
        m = fmaxf(m, __shfl_xor_sync(0xFFFFFFFFu, m, off));
    float s = expf(a - m) + ((lane < OUT_C - 32) ? expf(b - m) : 0.f);
#pragma unroll
    for (int off = 16; off > 0; off >>= 1)
        s += __shfl_xor_sync(0xFFFFFFFFu, s, off);
    float l = m + logf(s);
    row[lane] = a - l;
    if (lane < OUT_C - 32) row[lane + 32] = b - l;
}

// ---------------- launch ----------------
extern "C" void kernel_launch(void* const* d_in, const int* in_sizes, int n_in,
                              void* d_out, int out_size)
{
    const float* x0       = (const float*)d_in[0];   // [30000,128]
    const float* emb1     = (const float*)d_in[1];   // [20000,128]
    const float* rel_w1   = (const float*)d_in[2];   // [8,128,128] -> [1024][128]
    const float* root_w1  = (const float*)d_in[3];   // [2,128,128]
    const float* root_b1  = (const float*)d_in[4];   // [2,128]
    const float* rel_w2   = (const float*)d_in[5];   // [8,40,128] -> [320][128]
    const float* root_w2  = (const float*)d_in[6];   // [2,40,128]
    const float* root_b2  = (const float*)d_in[7];   // [2,40]
    const int*   edge_idx = (const int*)d_in[8];     // [2,600000]
    const int*   etype    = (const int*)d_in[9];     // [600000]
    // d_in[10] node_type / d_in[11] local_node_idx: layout is fixed (type-ordered), unused.
    (void)in_sizes; (void)n_in; (void)out_size;

    const int* src = edge_idx;
    const int* dst = edge_idx + N_EDGES;
    float* out = (float*)d_out;

    float *p_xt1 = nullptr, *p_h1 = nullptr, *p_xt2 = nullptr;
    cudaGetSymbolAddress((void**)&p_xt1, g_xt1);
    cudaGetSymbolAddress((void**)&p_h1,  g_h1);
    cudaGetSymbolAddress((void**)&p_xt2, g_xt2);

    // 1) counts
    zero_cnt_kernel<<<(NT * N_NODES + 255) / 256, 256>>>();
    count_kernel<<<(N_EDGES + 255) / 256, 256>>>(dst, etype);

    // 2) layer-1 GEMMs: rel transform (all 8 types as one [50000,128]x[128,1024]) + root
    sgemm_kernel<0, false, false, 8><<<dim3(782, 8), 256>>>(
        x0, emb1, rel_w1, nullptr, p_xt1, 0, N_NODES, NT * HID_C, NT * HID_C);
    sgemm_kernel<0, false, true, 8><<<dim3(469, 1), 256>>>(
        x0, emb1, root_w1, root_b1, p_h1, 0, N0, HID_C, HID_C);
    sgemm_kernel<0, false, true, 8><<<dim3(313, 1), 256>>>(
        x0, emb1, root_w1 + 128 * 128, root_b1 + 128, p_h1, N0, N_NODES - N0, HID_C, HID_C);

    // 3) layer-1 edge scatter-mean (atomics into g_h1)
    edge1_kernel<<<(N_EDGES * 32 + 255) / 256, 256>>>(src, dst, etype);

    // 4) layer-2 GEMMs (relu fused into A reads): rel [50000,128]x[128,320] + root into d_out
    sgemm_kernel<1, true, false, 4><<<dim3(782, 5), 256>>>(
        p_h1, nullptr, rel_w2, nullptr, p_xt2, 0, N_NODES, NT * OUT_C, NT * OUT_C);
    sgemm_kernel<1, true, true, 4><<<dim3(469, 1), 256>>>(
        p_h1, nullptr, root_w2, root_b2, out, 0, N0, OUT_C, OUT_C);
    sgemm_kernel<1, true, true, 4><<<dim3(313, 1), 256>>>(
        p_h1, nullptr, root_w2 + 40 * 128, root_b2 + 40, out, N0, N_NODES - N0, OUT_C, OUT_C);

    // 5) layer-2 edge scatter-mean (atomics into d_out)
    edge2_kernel<<<(N_EDGES * 32 + 255) / 256, 256>>>(src, dst, etype, out);

    // 6) log-softmax in place
    logsoftmax_kernel<<<(N_NODES * 32 + 255) / 256, 256>>>(out);
}

// round 4
// speedup vs baseline: 1.5207x; 1.5207x over previous
#include <cuda_runtime.h>
#include <cuda_bf16.h>
#include <cstdint>
#include <math.h>

// ---------------- problem constants ----------------
constexpr int N_NODES = 50000;
constexpr int N0      = 30000;
constexpr int N_EDGES = 600000;
constexpr int NT      = 8;
constexpr int K_AGG   = 1024;          // 8 relations x 128
constexpr int K_TOT   = 1152;          // + 128 root block
constexpr int KC      = 64;            // K per chunk
constexpr int NCHUNK  = K_TOT / KC;    // 18
constexpr int TILES0  = 235;           // ceil(30000/128)
constexpr int TILES1  = 157;           // ceil(20000/128)

// ---------------- device scratch ----------------
__device__ float g_agg[(size_t)N_NODES * K_AGG];   // 204.8 MB
__device__ float g_h1r[(size_t)N_NODES * 128];     // relu(h1), 25.6 MB
__device__ int   g_cnt[NT * N_NODES];
__device__ float g_inv[NT * N_NODES];
__device__ __align__(16) __nv_bfloat16 g_B1h[2 * 128 * K_TOT];
__device__ __align__(16) __nv_bfloat16 g_B1l[2 * 128 * K_TOT];
__device__ __align__(16) __nv_bfloat16 g_B2h[2 * 40 * K_TOT];
__device__ __align__(16) __nv_bfloat16 g_B2l[2 * 40 * K_TOT];

// ---------------- helpers ----------------
__device__ __forceinline__ uint32_t smem_u32(const void* p) {
    uint32_t a;
    asm("{ .reg .u64 t; cvta.to.shared.u64 t, %1; cvt.u32.u64 %0, t; }" : "=r"(a) : "l"(p));
    return a;
}
__device__ __forceinline__ uint32_t pack_bf16x2(float a, float b) {
    __nv_bfloat162 t = __floats2bfloat162_rn(a, b);
    return *reinterpret_cast<uint32_t*>(&t);
}
__device__ __forceinline__ void ldsm_x4(uint32_t addr, uint32_t* r) {
    asm volatile("ldmatrix.sync.aligned.m8n8.x4.shared.b16 {%0,%1,%2,%3}, [%4];"
                 : "=r"(r[0]), "=r"(r[1]), "=r"(r[2]), "=r"(r[3]) : "r"(addr));
}
__device__ __forceinline__ void ldsm_x2(uint32_t addr, uint32_t* r) {
    asm volatile("ldmatrix.sync.aligned.m8n8.x2.shared.b16 {%0,%1}, [%2];"
                 : "=r"(r[0]), "=r"(r[1]) : "r"(addr));
}
__device__ __forceinline__ void mma_bf16(float* c, const uint32_t* a, uint32_t b0, uint32_t b1) {
    asm volatile(
        "mma.sync.aligned.m16n8k16.row.col.f32.bf16.bf16.f32 "
        "{%0,%1,%2,%3}, {%4,%5,%6,%7}, {%8,%9}, {%0,%1,%2,%3};"
        : "+f"(c[0]), "+f"(c[1]), "+f"(c[2]), "+f"(c[3])
        : "r"(a[0]), "r"(a[1]), "r"(a[2]), "r"(a[3]), "r"(b0), "r"(b1));
}

// ---------------- small kernels ----------------
__global__ void count_kernel(const int* __restrict__ dst, const int* __restrict__ et) {
    int e = blockIdx.x * blockDim.x + threadIdx.x;
    if (e < N_EDGES) atomicAdd(&g_cnt[et[e] * N_NODES + dst[e]], 1);
}
__global__ void inv_kernel() {
    int i = blockIdx.x * blockDim.x + threadIdx.x;
    if (i < NT * N_NODES) {
        int c = g_cnt[i];
        g_inv[i] = 1.0f / (float)(c < 1 ? 1 : c);
    }
}

// scatter-mean accumulate: agg[dst][t*128 + c] += src_feat[c] * inv(t,dst)
template<int SRC>
__global__ void edge_kernel(const int* __restrict__ src, const int* __restrict__ dst,
                            const int* __restrict__ et,
                            const float* __restrict__ R0, const float* __restrict__ R1)
{
    int e = (blockIdx.x * blockDim.x + threadIdx.x) >> 5;
    if (e >= N_EDGES) return;
    int lane = threadIdx.x & 31;
    int s = src[e], d = dst[e], t = et[e];
    float inv = g_inv[t * N_NODES + d];
    const float* xs;
    if (SRC == 0) xs = (s < N0) ? (R0 + (size_t)s * 128) : (R1 + (size_t)(s - N0) * 128);
    else          xs = R0 + (size_t)s * 128;
    float4 v = reinterpret_cast<const float4*>(xs)[lane];
    float* op = g_agg + (size_t)d * K_AGG + t * 128 + lane * 4;
    atomicAdd(op + 0, v.x * inv);
    atomicAdd(op + 1, v.y * inv);
    atomicAdd(op + 2, v.z * inv);
    atomicAdd(op + 3, v.w * inv);
}

// B prep: split weights into bf16 hi/lo. Layout Bh[var][n][k]; k<1024 rel, else root(var).
template<int NB>
__global__ void prepB_kernel(const float* __restrict__ rel_w, const float* __restrict__ root_w,
                             __nv_bfloat16* __restrict__ Bh, __nv_bfloat16* __restrict__ Bl)
{
    int i = blockIdx.x * blockDim.x + threadIdx.x;
    if (i >= 2 * NB * K_TOT) return;
    int k = i % K_TOT;
    int n = (i / K_TOT) % NB;
    int v = i / (K_TOT * NB);
    float w = (k < K_AGG) ? rel_w[(k >> 7) * NB * 128 + n * 128 + (k & 127)]
                          : root_w[v * NB * 128 + n * 128 + (k - K_AGG)];
    __nv_bfloat16 h = __float2bfloat16(w);
    Bh[i] = h;
    Bl[i] = __float2bfloat16(w - __bfloat162float(h));
}

// ---------------- bf16x3 mma.sync GEMM ----------------
// D[row][n] = sum_k A[row][k] * B[var(row)][n][k],  K = 1152 (16 agg chunks + 2 root chunks)
// EPI 0: out = relu(D + bias)            -> outp[row*128 + n]
// EPI 1: out = log_softmax(D + bias)     -> outp[row*40  + n]
template<int NB, int SRC, int EPI>
__global__ void __launch_bounds__(256, 2) gemm_kernel(
    const float* __restrict__ R0, const float* __restrict__ R1,
    const __nv_bfloat16* __restrict__ Bh, const __nv_bfloat16* __restrict__ Bl,
    const float* __restrict__ bias, float* __restrict__ outp)
{
    constexpr int WARPS_M = (NB == 128) ? 4 : 8;
    constexpr int WARPS_N = (NB == 128) ? 2 : 1;
    constexpr int WM = 128 / WARPS_M;          // 32 or 16
    constexpr int WN = NB / WARPS_N;           // 64 or 40
    constexpr int MF = WM / 16;                // 2 or 1
    constexpr int NF = WN / 8;                 // 8 or 5
    constexpr int A_BYTES = 128 * KC * 2;      // 16384
    constexpr int B_BYTES = NB * KC * 2;

    extern __shared__ char smem[];
    char* sAh = smem;
    char* sAl = smem + A_BYTES;
    char* sBh = smem + 2 * A_BYTES;
    char* sBl = smem + 2 * A_BYTES + B_BYTES;
    const uint32_t uAh = smem_u32(sAh), uAl = uAh + A_BYTES;
    const uint32_t uBh = uAh + 2 * A_BYTES, uBl = uBh + B_BYTES;

    const int tid  = threadIdx.x;
    const int wid  = tid >> 5;
    const int lane = tid & 31;
    const int warpM = wid % WARPS_M;
    const int warpN = wid / WARPS_M;

    const int bx = blockIdx.x;
    const int var = (bx < TILES0) ? 0 : 1;
    const int mrow0 = var ? (N0 + (bx - TILES0) * 128) : (bx * 128);
    const int row_end = var ? N_NODES : N0;
    const __nv_bfloat16* Bhv = Bh + (size_t)var * NB * K_TOT;
    const __nv_bfloat16* Blv = Bl + (size_t)var * NB * K_TOT;
    const float* biasv = bias + var * NB;

    float acc[MF][NF][4];
#pragma unroll
    for (int i = 0; i < MF; i++)
#pragma unroll
        for (int j = 0; j < NF; j++)
#pragma unroll
            for (int q = 0; q < 4; q++) acc[i][j][q] = 0.f;

    for (int c = 0; c < NCHUNK; c++) {
        // ---- A: 128 rows x 64 fp32 -> bf16 hi/lo, 16B-XOR swizzled smem ----
#pragma unroll
        for (int i = 0; i < 4; i++) {
            int idx = tid + i * 256;       // 0..1023 -> (row, 16B-unit)
            int row = idx >> 3;
            int u = idx & 7;
            int grow = mrow0 + row;
            float4 v0 = make_float4(0.f, 0.f, 0.f, 0.f), v1 = v0;
            if (grow < row_end) {
                const float* ap;
                if (c < 16) {
                    ap = g_agg + (size_t)grow * K_AGG + c * KC + u * 8;
                } else {
                    int off = (c - 16) * KC + u * 8;
                    if (SRC == 0)
                        ap = (grow < N0) ? (R0 + (size_t)grow * 128 + off)
                                         : (R1 + (size_t)(grow - N0) * 128 + off);
                    else
                        ap = R0 + (size_t)grow * 128 + off;
                }
                v0 = *reinterpret_cast<const float4*>(ap);
                v1 = *reinterpret_cast<const float4*>(ap + 4);
            }
            uint4 hv, lv;
            hv.x = pack_bf16x2(v0.x, v0.y); hv.y = pack_bf16x2(v0.z, v0.w);
            hv.z = pack_bf16x2(v1.x, v1.y); hv.w = pack_bf16x2(v1.z, v1.w);
            float l0 = v0.x - __bfloat162float(__float2bfloat16(v0.x));
            float l1 = v0.y - __bfloat162float(__float2bfloat16(v0.y));
            float l2 = v0.z - __bfloat162float(__float2bfloat16(v0.z));
            float l3 = v0.w - __bfloat162float(__float2bfloat16(v0.w));
            float l4 = v1.x - __bfloat162float(__float2bfloat16(v1.x));
            float l5 = v1.y - __bfloat162float(__float2bfloat16(v1.y));
            float l6 = v1.z - __bfloat162float(__float2bfloat16(v1.z));
            float l7 = v1.w - __bfloat162float(__float2bfloat16(v1.w));
            lv.x = pack_bf16x2(l0, l1); lv.y = pack_bf16x2(l2, l3);
            lv.z = pack_bf16x2(l4, l5); lv.w = pack_bf16x2(l6, l7);
            uint32_t off = row * 128 + ((u ^ (row & 7)) << 4);
            *reinterpret_cast<uint4*>(sAh + off) = hv;
            *reinterpret_cast<uint4*>(sAl + off) = lv;
        }
        // ---- B: NB rows x 64 bf16 (hi & lo), swizzled ----
        constexpr int BU = NB * 8;
        for (int idx = tid; idx < 2 * BU; idx += 256) {
            int isLo = idx >= BU;
            int ii = isLo ? idx - BU : idx;
            int n = ii >> 3;
            int u = ii & 7;
            uint4 val = *reinterpret_cast<const uint4*>(
                (isLo ? Blv : Bhv) + (size_t)n * K_TOT + c * KC + u * 8);
            uint32_t off = n * 128 + ((u ^ (n & 7)) << 4);
            *reinterpret_cast<uint4*>((isLo ? sBl : sBh) + off) = val;
        }
        __syncthreads();

        // ---- compute: 3 passes (AhBh, AhBl, AlBh) x 4 k16 steps ----
#pragma unroll
        for (int p = 0; p < 3; p++) {
            uint32_t aBase = (p == 2) ? uAl : uAh;
            uint32_t bBase = (p == 1) ? uBl : uBh;
#pragma unroll
            for (int ks = 0; ks < 4; ks++) {
                uint32_t a[MF][4];
#pragma unroll
                for (int mf = 0; mf < MF; mf++) {
                    int row = warpM * WM + mf * 16 + (lane & 15);
                    int u = 2 * ks + (lane >> 4);
                    ldsm_x4(aBase + row * 128 + ((u ^ (row & 7)) << 4), a[mf]);
                }
#pragma unroll
                for (int nfp = 0; nfp < NF / 2; nfp++) {
                    int nrow = warpN * WN + nfp * 16 + ((lane >> 4) * 8) + (lane & 7);
                    int u = 2 * ks + ((lane >> 3) & 1);
                    uint32_t b[4];
                    ldsm_x4(bBase + nrow * 128 + ((u ^ (nrow & 7)) << 4), b);
#pragma unroll
                    for (int mf = 0; mf < MF; mf++) {
                        mma_bf16(acc[mf][2 * nfp + 0], a[mf], b[0], b[1]);
                        mma_bf16(acc[mf][2 * nfp + 1], a[mf], b[2], b[3]);
                    }
                }
                if (NF & 1) {
                    int l = lane & 15;
                    int nrow = warpN * WN + (NF - 1) * 8 + (l & 7);
                    int u = 2 * ks + (l >> 3);
                    uint32_t b[2];
                    ldsm_x2(bBase + nrow * 128 + ((u ^ (nrow & 7)) << 4), b);
#pragma unroll
                    for (int mf = 0; mf < MF; mf++)
                        mma_bf16(acc[mf][NF - 1], a[mf], b[0], b[1]);
                }
            }
        }
        __syncthreads();
    }

    // ---- epilogue ----
    if (EPI == 0) {
#pragma unroll
        for (int mf = 0; mf < MF; mf++) {
#pragma unroll
            for (int nf = 0; nf < NF; nf++) {
                int col = warpN * WN + nf * 8 + (lane & 3) * 2;
                float b0 = biasv[col], b1 = biasv[col + 1];
                int r0 = mrow0 + warpM * WM + mf * 16 + (lane >> 2);
                if (r0 < row_end) {
                    float2 v = make_float2(fmaxf(acc[mf][nf][0] + b0, 0.f),
                                           fmaxf(acc[mf][nf][1] + b1, 0.f));
                    *reinterpret_cast<float2*>(outp + (size_t)r0 * 128 + col) = v;
                }
                int r1 = r0 + 8;
                if (r1 < row_end) {
                    float2 v = make_float2(fmaxf(acc[mf][nf][2] + b0, 0.f),
                                           fmaxf(acc[mf][nf][3] + b1, 0.f));
                    *reinterpret_cast<float2*>(outp + (size_t)r1 * 128 + col) = v;
                }
            }
        }
    } else {
#pragma unroll
        for (int h = 0; h < 2; h++) {              // h=0: rows r, h=1: rows r+8
            int row = mrow0 + wid * 16 + (lane >> 2) + h * 8;
            float v[2 * NF];
            float m = -INFINITY;
#pragma unroll
            for (int f = 0; f < NF; f++) {
                int col = f * 8 + (lane & 3) * 2;
                v[2 * f + 0] = acc[0][f][2 * h + 0] + biasv[col];
                v[2 * f + 1] = acc[0][f][2 * h + 1] + biasv[col + 1];
                m = fmaxf(m, fmaxf(v[2 * f], v[2 * f + 1]));
            }
            m = fmaxf(m, __shfl_xor_sync(0xFFFFFFFFu, m, 1));
            m = fmaxf(m, __shfl_xor_sync(0xFFFFFFFFu, m, 2));
            float s = 0.f;
#pragma unroll
            for (int j = 0; j < 2 * NF; j++) s += expf(v[j] - m);
            s += __shfl_xor_sync(0xFFFFFFFFu, s, 1);
            s += __shfl_xor_sync(0xFFFFFFFFu, s, 2);
            float l = m + logf(s);
            if (row < row_end) {
#pragma unroll
                for (int f = 0; f < NF; f++) {
                    int col = f * 8 + (lane & 3) * 2;
                    float2 o = make_float2(v[2 * f] - l, v[2 * f + 1] - l);
                    *reinterpret_cast<float2*>(outp + (size_t)row * NB + col) = o;
                }
            }
        }
    }
}

// ---------------- launch ----------------
extern "C" void kernel_launch(void* const* d_in, const int* in_sizes, int n_in,
                              void* d_out, int out_size)
{
    const float* x0      = (const float*)d_in[0];
    const float* emb1    = (const float*)d_in[1];
    const float* rel_w1  = (const float*)d_in[2];
    const float* root_w1 = (const float*)d_in[3];
    const float* root_b1 = (const float*)d_in[4];
    const float* rel_w2  = (const float*)d_in[5];
    const float* root_w2 = (const float*)d_in[6];
    const float* root_b2 = (const float*)d_in[7];
    const int*   eidx    = (const int*)d_in[8];
    const int*   etype   = (const int*)d_in[9];
    (void)in_sizes; (void)n_in; (void)out_size;

    const int* src = eidx;
    const int* dst = eidx + N_EDGES;
    float* out = (float*)d_out;

    void *p_agg, *p_cnt, *p_h1r, *p_B1h, *p_B1l, *p_B2h, *p_B2l;
    cudaGetSymbolAddress(&p_agg, g_agg);
    cudaGetSymbolAddress(&p_cnt, g_cnt);
    cudaGetSymbolAddress(&p_h1r, g_h1r);
    cudaGetSymbolAddress(&p_B1h, g_B1h);
    cudaGetSymbolAddress(&p_B1l, g_B1l);
    cudaGetSymbolAddress(&p_B2h, g_B2h);
    cudaGetSymbolAddress(&p_B2l, g_B2l);

    constexpr int SMEM1 = 2 * 128 * KC * 2 + 2 * 128 * KC * 2;   // 65536
    constexpr int SMEM2 = 2 * 128 * KC * 2 + 2 * 40 * KC * 2;    // 43008
    cudaFuncSetAttribute(gemm_kernel<128, 0, 0>, cudaFuncAttributeMaxDynamicSharedMemorySize, SMEM1);
    cudaFuncSetAttribute(gemm_kernel<40, 1, 1>,  cudaFuncAttributeMaxDynamicSharedMemorySize, SMEM2);

    // B weight split (tiny)
    prepB_kernel<128><<<(2 * 128 * K_TOT + 255) / 256, 256>>>(
        rel_w1, root_w1, (__nv_bfloat16*)p_B1h, (__nv_bfloat16*)p_B1l);
    prepB_kernel<40><<<(2 * 40 * K_TOT + 255) / 256, 256>>>(
        rel_w2, root_w2, (__nv_bfloat16*)p_B2h, (__nv_bfloat16*)p_B2l);

    // counts + inverse means
    cudaMemsetAsync(p_cnt, 0, sizeof(int) * NT * N_NODES);
    count_kernel<<<(N_EDGES + 255) / 256, 256>>>(dst, etype);
    inv_kernel<<<(NT * N_NODES + 255) / 256, 256>>>();

    // layer-1 aggregation + fused GEMM (rel + root + bias + relu) -> g_h1r
    cudaMemsetAsync(p_agg, 0, sizeof(float) * (size_t)N_NODES * K_AGG);
    edge_kernel<0><<<(N_EDGES * 32 + 255) / 256, 256>>>(src, dst, etype, x0, emb1);
    gemm_kernel<128, 0, 0><<<TILES0 + TILES1, 256, SMEM1>>>(
        x0, emb1, (const __nv_bfloat16*)p_B1h, (const __nv_bfloat16*)p_B1l,
        root_b1, (float*)p_h1r);

    // layer-2 aggregation + fused GEMM (rel + root + bias + log_softmax) -> d_out
    cudaMemsetAsync(p_agg, 0, sizeof(float) * (size_t)N_NODES * K_AGG);
    edge_kernel<1><<<(N_EDGES * 32 + 255) / 256, 256>>>(src, dst, etype, (const float*)p_h1r, nullptr);
    gemm_kernel<40, 1, 1><<<TILES0 + TILES1, 256, SMEM2>>>(
        (const float*)p_h1r, nullptr, (const __nv_bfloat16*)p_B2h, (const __nv_bfloat16*)p_B2l,
        root_b2, out);
}